// round 8
// baseline (speedup 1.0000x reference)
#include <cuda_runtime.h>
#include <cuda_bf16.h>

// Distance_26379689132772: dense radius_graph over N=8192 atoms, 128 atoms/mol.
// Output layout (f32): [0, N*N)       edge_weight (row-major [i,j])
//                      [N*N, 2*N*N)  mask as 0.0/1.0
//
// 98.4% of the output is zero (only 64 diagonal 128x128 molecule blocks are
// live). Strategy: graph memset node zeros the whole 512MB (fill path), then
// a small kernel overwrites only the diagonal blocks (8MB).

#define NATOMS 8192
#define CUT_HI 5.0f
#define NN     ((size_t)NATOMS * NATOMS)   // floats per plane
#define MOL    128

// One block = 8 rows of one molecule's 128x128 diagonal block.
// grid.x = 64 molecules * 16 row-groups = 1024 blocks, 256 threads.
// Thread t: warp w = t/32 -> row r = 8*rowgrp + w; lane handles 4 cols.
__global__ __launch_bounds__(256)
void diag_kernel(const float* __restrict__ pos,
                 float*       __restrict__ out)
{
    int mol    = blockIdx.x >> 4;          // 0..63
    int rowgrp = blockIdx.x & 15;          // 0..15
    int w      = threadIdx.x >> 5;         // warp in block, 0..7
    int lane   = threadIdx.x & 31;

    int li = rowgrp * 8 + w;               // local row 0..127
    int i  = mol * MOL + li;               // global row
    int j0 = mol * MOL + lane * 4;         // global col of this lane's quad

    float xi = __ldg(pos + 3 * i + 0);
    float yi = __ldg(pos + 3 * i + 1);
    float zi = __ldg(pos + 3 * i + 2);
    float sqi = xi * xi + yi * yi + zi * zi;

    float wv[4], mv[4];
    #pragma unroll
    for (int k = 0; k < 4; k++) {
        int jj = j0 + k;
        float xj = __ldg(pos + 3 * jj + 0);
        float yj = __ldg(pos + 3 * jj + 1);
        float zj = __ldg(pos + 3 * jj + 2);
        float sqj = xj * xj + yj * yj + zj * zj;
        // Gram trick, matching the reference's arithmetic path.
        float d2 = sqi + sqj - 2.0f * (xi * xj + yi * yj + zi * zj);
        d2 = fmaxf(d2, 0.0f);
        float d = (d2 > 0.0f) ? sqrtf(d2) : 0.0f;
        bool mask = (i != jj) && (d <= CUT_HI);
        wv[k] = mask ? d : 0.0f;
        mv[k] = mask ? 1.0f : 0.0f;
    }

    size_t off = (size_t)i * NATOMS + (size_t)j0;
    float4* pw = (float4*)(out + off);
    float4* pm = (float4*)(out + NN + off);
    *pw = make_float4(wv[0], wv[1], wv[2], wv[3]);
    *pm = make_float4(mv[0], mv[1], mv[2], mv[3]);
}

extern "C" void kernel_launch(void* const* d_in, const int* in_sizes, int n_in,
                              void* d_out, int out_size)
{
    const float* pos = (const float*)d_in[0];
    float*       out = (float*)d_out;

    // Zero both planes via a graph memset node (capturable, async).
    cudaMemsetAsync(d_out, 0, 2 * NN * sizeof(float));

    // Overwrite the 64 diagonal molecule blocks (stream-ordered after memset).
    diag_kernel<<<64 * 16, 256>>>(pos, out);
}